// round 3
// baseline (speedup 1.0000x reference)
#include <cuda_runtime.h>
#include <math_constants.h>

#define BATCH 8
#define NPTS  4096
#define TPB   256
#define CHUNK 2048

// Scratch: packed DB points (-2x, -2y, -2z, |p|^2) for each direction's database.
// [0] = packed tar (DB for accuracy direction), [1] = packed src (DB for complete direction)
__device__ float4 g_packed[2][BATCH * NPTS];
__device__ float  g_accum[2];   // [0] = sum over tar of min-dist (complete), [1] = sum over src (accuracy)

// Pack both point clouds and zero the accumulators (stream-ordered before chamfer kernel).
__global__ void pack_kernel(const float* __restrict__ tar, const float* __restrict__ src) {
    int i = blockIdx.x * blockDim.x + threadIdx.x;
    if (i == 0) { g_accum[0] = 0.f; g_accum[1] = 0.f; }
    if (i < BATCH * NPTS) {
        float x = tar[3 * i + 0], y = tar[3 * i + 1], z = tar[3 * i + 2];
        g_packed[0][i] = make_float4(-2.f * x, -2.f * y, -2.f * z,
                                     fmaf(x, x, fmaf(y, y, z * z)));
        x = src[3 * i + 0]; y = src[3 * i + 1]; z = src[3 * i + 2];
        g_packed[1][i] = make_float4(-2.f * x, -2.f * y, -2.f * z,
                                     fmaf(x, x, fmaf(y, y, z * z)));
    }
}

// One block = 256 query points of one batch, one direction.
// grid = (NPTS/TPB, BATCH, 2).  dir 0: queries = tar, DB = packed src  -> complete
//                               dir 1: queries = src, DB = packed tar  -> accuracy
__global__ __launch_bounds__(TPB, 2)
void chamfer_kernel(const float* __restrict__ tar, const float* __restrict__ src) {
    const int dir = blockIdx.z;
    const float*  qbase = (dir == 0) ? tar : src;
    const float4* db    = g_packed[(dir == 0) ? 1 : 0];

    const int b  = blockIdx.y;
    const int qi = blockIdx.x * TPB + threadIdx.x;

    const float* q = qbase + (size_t)(b * NPTS + qi) * 3;
    const float qx = q[0], qy = q[1], qz = q[2];
    const float qn = fmaf(qx, qx, fmaf(qy, qy, qz * qz));

    const float4* dbb = db + (size_t)b * NPTS;

    __shared__ float4 s[CHUNK];

    float mn0 = CUDART_INF_F, mn1 = CUDART_INF_F;
    float mn2 = CUDART_INF_F, mn3 = CUDART_INF_F;

    for (int c0 = 0; c0 < NPTS; c0 += CHUNK) {
        __syncthreads();
        #pragma unroll
        for (int j = threadIdx.x; j < CHUNK; j += TPB)
            s[j] = dbb[c0 + j];
        __syncthreads();

        #pragma unroll 2
        for (int j = 0; j < CHUNK; j += 4) {
            float4 p0 = s[j + 0];
            float4 p1 = s[j + 1];
            float4 p2 = s[j + 2];
            float4 p3 = s[j + 3];
            mn0 = fminf(mn0, fmaf(qx, p0.x, fmaf(qy, p0.y, fmaf(qz, p0.z, p0.w))));
            mn1 = fminf(mn1, fmaf(qx, p1.x, fmaf(qy, p1.y, fmaf(qz, p1.z, p1.w))));
            mn2 = fminf(mn2, fmaf(qx, p2.x, fmaf(qy, p2.y, fmaf(qz, p2.z, p2.w))));
            mn3 = fminf(mn3, fmaf(qx, p3.x, fmaf(qy, p3.y, fmaf(qz, p3.z, p3.w))));
        }
    }

    float mn = fminf(fminf(mn0, mn1), fminf(mn2, mn3));
    float d  = sqrtf(fmaxf(qn + mn, 0.f));

    // Block-wide sum of distances, then one atomic per block.
    #pragma unroll
    for (int o = 16; o > 0; o >>= 1)
        d += __shfl_down_sync(0xffffffffu, d, o);

    __shared__ float ws[TPB / 32];
    const int w = threadIdx.x >> 5, l = threadIdx.x & 31;
    if (l == 0) ws[w] = d;
    __syncthreads();
    if (threadIdx.x == 0) {
        float sblk = 0.f;
        #pragma unroll
        for (int i = 0; i < TPB / 32; i++) sblk += ws[i];
        atomicAdd(&g_accum[dir], sblk);
    }
}

__global__ void finalize_kernel(float* __restrict__ out) {
    if (threadIdx.x == 0) {
        const float inv = 1.f / (float)(BATCH * NPTS);
        float complete = g_accum[0] * inv;
        float accuracy = g_accum[1] * inv;
        out[0] = accuracy;
        out[1] = complete;
        out[2] = 0.5f * (accuracy + complete);
    }
}

extern "C" void kernel_launch(void* const* d_in, const int* in_sizes, int n_in,
                              void* d_out, int out_size) {
    const float* tar = (const float*)d_in[0];
    const float* src = (const float*)d_in[1];
    float* out = (float*)d_out;

    pack_kernel<<<(BATCH * NPTS + 255) / 256, 256>>>(tar, src);
    chamfer_kernel<<<dim3(NPTS / TPB, BATCH, 2), TPB>>>(tar, src);
    finalize_kernel<<<1, 32>>>(out);
}

// round 4
// speedup vs baseline: 1.5347x; 1.5347x over previous
#include <cuda_runtime.h>
#include <math_constants.h>

#define BATCH 8
#define NPTS  4096
#define TPB   128          // threads per block
#define QPT   2            // queries per thread -> block covers 256 queries
#define QPB   (TPB * QPT)  // 256
#define GX    (NPTS / QPB) // 16
#define CHUNK 2048         // DB points resident in smem per stage

// per-block partial sums: [dir][batch][blockIdx.x] flattened -> 2*8*16 = 256
__device__ float g_partials[2 * BATCH * GX];

// ---- f32x2 helpers -------------------------------------------------------
__device__ __forceinline__ unsigned long long pk(float lo, float hi) {
    unsigned long long r;
    asm("mov.b64 %0, {%1, %2};" : "=l"(r) : "f"(lo), "f"(hi));
    return r;
}
__device__ __forceinline__ unsigned long long fma2(unsigned long long a,
                                                   unsigned long long b,
                                                   unsigned long long c) {
    unsigned long long r;
    asm("fma.rn.f32x2 %0, %1, %2, %3;" : "=l"(r) : "l"(a), "l"(b), "l"(c));
    return r;
}
__device__ __forceinline__ void unpk(unsigned long long v, float& lo, float& hi) {
    asm("mov.b64 {%0, %1}, %2;" : "=f"(lo), "=f"(hi) : "l"(v));
}

// One block = 256 query points (2 per thread) of one batch, one direction.
// grid = (GX, BATCH, 2). dir 0: queries=tar, DB=src -> complete
//                        dir 1: queries=src, DB=tar -> accuracy
__global__ __launch_bounds__(TPB, 2)
void chamfer_kernel(const float* __restrict__ tar, const float* __restrict__ src) {
    const int dir = blockIdx.z;
    const float* qraw = (dir == 0) ? tar : src;
    const float* draw = (dir == 0) ? src : tar;

    const int b   = blockIdx.y;
    const int tid = threadIdx.x;

    // two queries per thread, stride TPB for coalesced loads
    const int q0i = blockIdx.x * QPB + tid;
    const int q1i = q0i + TPB;

    const float* q0p = qraw + (size_t)(b * NPTS + q0i) * 3;
    const float* q1p = qraw + (size_t)(b * NPTS + q1i) * 3;
    const float q0x = q0p[0], q0y = q0p[1], q0z = q0p[2];
    const float q1x = q1p[0], q1y = q1p[1], q1z = q1p[2];
    const float qn0 = fmaf(q0x, q0x, fmaf(q0y, q0y, q0z * q0z));
    const float qn1 = fmaf(q1x, q1x, fmaf(q1y, q1y, q1z * q1z));

    const unsigned long long q0x2 = pk(q0x, q0x), q0y2 = pk(q0y, q0y), q0z2 = pk(q0z, q0z);
    const unsigned long long q1x2 = pk(q1x, q1x), q1y2 = pk(q1y, q1y), q1z2 = pk(q1z, q1z);

    const float* dbb = draw + (size_t)b * NPTS * 3;

    // pair-SoA smem: sA[j] = {pack(-2x0,-2x1), pack(-2y0,-2y1)}
    //                sB[j] = {pack(-2z0,-2z1), pack(|p0|^2,|p1|^2)}
    __shared__ ulonglong2 sA[CHUNK / 2];
    __shared__ ulonglong2 sB[CHUNK / 2];

    float a0 = CUDART_INF_F, a1 = CUDART_INF_F, a2 = CUDART_INF_F, a3 = CUDART_INF_F; // q0 mins
    float b0 = CUDART_INF_F, b1 = CUDART_INF_F, b2 = CUDART_INF_F, b3 = CUDART_INF_F; // q1 mins

    for (int c0 = 0; c0 < NPTS; c0 += CHUNK) {
        __syncthreads();
        // fill + pack on the fly (replaces the separate pack kernel)
        for (int j = tid; j < CHUNK / 2; j += TPB) {
            const float2* p2 = (const float2*)(dbb + (size_t)(c0 + 2 * j) * 3);
            float2 v0 = p2[0], v1 = p2[1], v2 = p2[2];
            // point0 = (v0.x, v0.y, v1.x), point1 = (v1.y, v2.x, v2.y)
            float n0 = fmaf(v0.x, v0.x, fmaf(v0.y, v0.y, v1.x * v1.x));
            float n1 = fmaf(v1.y, v1.y, fmaf(v2.x, v2.x, v2.y * v2.y));
            sA[j] = make_ulonglong2(pk(-2.f * v0.x, -2.f * v1.y),
                                    pk(-2.f * v0.y, -2.f * v2.x));
            sB[j] = make_ulonglong2(pk(-2.f * v1.x, -2.f * v2.y),
                                    pk(n0, n1));
        }
        __syncthreads();

        #pragma unroll 4
        for (int j = 0; j < CHUNK / 2; j += 2) {
            ulonglong2 pa0 = sA[j + 0];
            ulonglong2 pb0 = sB[j + 0];
            ulonglong2 pa1 = sA[j + 1];
            ulonglong2 pb1 = sB[j + 1];

            // pair 0
            {
                unsigned long long t = fma2(q0z2, pb0.x, pb0.y);
                t = fma2(q0y2, pa0.y, t);
                t = fma2(q0x2, pa0.x, t);
                float lo, hi; unpk(t, lo, hi);
                a0 = fminf(a0, lo); a1 = fminf(a1, hi);

                t = fma2(q1z2, pb0.x, pb0.y);
                t = fma2(q1y2, pa0.y, t);
                t = fma2(q1x2, pa0.x, t);
                unpk(t, lo, hi);
                b0 = fminf(b0, lo); b1 = fminf(b1, hi);
            }
            // pair 1
            {
                unsigned long long t = fma2(q0z2, pb1.x, pb1.y);
                t = fma2(q0y2, pa1.y, t);
                t = fma2(q0x2, pa1.x, t);
                float lo, hi; unpk(t, lo, hi);
                a2 = fminf(a2, lo); a3 = fminf(a3, hi);

                t = fma2(q1z2, pb1.x, pb1.y);
                t = fma2(q1y2, pa1.y, t);
                t = fma2(q1x2, pa1.x, t);
                unpk(t, lo, hi);
                b2 = fminf(b2, lo); b3 = fminf(b3, hi);
            }
        }
    }

    float mn0 = fminf(fminf(a0, a1), fminf(a2, a3));
    float mn1 = fminf(fminf(b0, b1), fminf(b2, b3));
    float d = sqrtf(fmaxf(qn0 + mn0, 0.f)) + sqrtf(fmaxf(qn1 + mn1, 0.f));

    // block-wide sum, one partials slot per block (no atomics, no pre-zeroing)
    #pragma unroll
    for (int o = 16; o > 0; o >>= 1)
        d += __shfl_down_sync(0xffffffffu, d, o);

    __shared__ float ws[TPB / 32];
    const int w = tid >> 5, l = tid & 31;
    if (l == 0) ws[w] = d;
    __syncthreads();
    if (tid == 0) {
        float sblk = 0.f;
        #pragma unroll
        for (int i = 0; i < TPB / 32; i++) sblk += ws[i];
        g_partials[(blockIdx.z * BATCH + blockIdx.y) * GX + blockIdx.x] = sblk;
    }
}

__global__ void finalize_kernel(float* __restrict__ out) {
    const int t = threadIdx.x;  // 256 threads, one per partial
    float v = g_partials[t];
    #pragma unroll
    for (int o = 16; o > 0; o >>= 1)
        v += __shfl_down_sync(0xffffffffu, v, o);

    __shared__ float ws[8];
    if ((t & 31) == 0) ws[t >> 5] = v;
    __syncthreads();
    if (t == 0) {
        const float inv = 1.f / (float)(BATCH * NPTS);
        float complete = (ws[0] + ws[1] + ws[2] + ws[3]) * inv;  // dir 0
        float accuracy = (ws[4] + ws[5] + ws[6] + ws[7]) * inv;  // dir 1
        out[0] = accuracy;
        out[1] = complete;
        out[2] = 0.5f * (accuracy + complete);
    }
}

extern "C" void kernel_launch(void* const* d_in, const int* in_sizes, int n_in,
                              void* d_out, int out_size) {
    const float* tar = (const float*)d_in[0];
    const float* src = (const float*)d_in[1];
    float* out = (float*)d_out;

    chamfer_kernel<<<dim3(GX, BATCH, 2), TPB>>>(tar, src);
    finalize_kernel<<<1, 256>>>(out);
}